// round 13
// baseline (speedup 1.0000x reference)
#include <cuda_runtime.h>
#include <cuda_bf16.h>

// EquiConv fused kernel: 8 edges/warp (NT=128), A-factored ss contraction,
// register-prefetched weight staging, packed f32x2 FMA throughout.
// E=20000, S=64, V=32, FC_IN=128, HID=64. out (E,160).

#define TE 32      // edges per block (20000/32 = 625 blocks exactly)
#define NT 128     // 4 warps; each warp owns 8 edges
#define KC 32      // K chunk
#define NCH 160    // chunks: 128 ss + 32 vv

#define INV_SQRT3_F 0.5773502691896258f
#define A_SC_F 0.013975424859373686f   // 1/sqrt(64*64+32*32)
#define A_VEC_F 0.015625f              // 1/sqrt(2*64*32)

// shared layout (floats)
#define OFF_X1ST 0                 // [64][36]  transposed x1s
#define OFF_X2ST 2304              // [64][36]
#define OFF_X1V  4608              // [32][97]
#define OFF_X2V  7712              // [32][97]
#define OFF_WOUT 10816             // [32][96]
#define OFF_SIG  13888             // [32][32]
#define OFF_UN   14912             // 4096 union: {MLP fw/h2} / {Wc 3072 + Pc 1024} / {vec 4096}
#define SMEM_FLOATS 19008          // 76032 bytes (x3 blocks/SM)

typedef unsigned long long u64t;

__device__ __forceinline__ float sigmoidf_(float x) {
    return __fdividef(1.0f, 1.0f + __expf(-x));
}
__device__ __forceinline__ u64t splat2(float w) {
    u64t r;
    unsigned int wi = __float_as_uint(w);
    asm("mov.b64 %0, {%1, %1};" : "=l"(r) : "r"(wi));
    return r;
}
__device__ __forceinline__ void fma2(u64t& d, u64t a, u64t b) {
    asm("fma.rn.f32x2 %0, %1, %2, %0;" : "+l"(d) : "l"(a), "l"(b));
}
__device__ __forceinline__ float2 unpack2(u64t v) {
    unsigned int lo, hi;
    asm("mov.b64 {%0, %1}, %2;" : "=r"(lo), "=r"(hi) : "l"(v));
    float2 f;
    f.x = __uint_as_float(lo);
    f.y = __uint_as_float(hi);
    return f;
}

__global__ __launch_bounds__(NT, 3) void equiconv_kernel(
    const float* __restrict__ fea_in1,
    const float* __restrict__ fea_in2,
    const float* __restrict__ fea_weight,
    const float* __restrict__ wsss,   // (64,64,64)  k*64 + w   (k = u*64+v)
    const float* __restrict__ wvvs,   // (32,32,64)
    const float* __restrict__ wssg,   // (64,64,32)
    const float* __restrict__ wvvg,   // (32,32,32)
    const float* __restrict__ wsvv,   // (64,32,32)  u*1024 + v*32 + w
    const float* __restrict__ wvsv,   // (32,64,32)  u*2048 + v*32 + w
    const float* __restrict__ fw1, const float* __restrict__ fb1,
    const float* __restrict__ fw2, const float* __restrict__ fb2,
    const float* __restrict__ fw3, const float* __restrict__ fb3,
    float* __restrict__ out)
{
    extern __shared__ float smem[];
    float* s_x1sT = smem + OFF_X1ST;
    float* s_x2sT = smem + OFF_X2ST;
    float* s_x1v  = smem + OFF_X1V;
    float* s_x2v  = smem + OFF_X2V;
    float* s_wout = smem + OFF_WOUT;
    float* s_sig  = smem + OFF_SIG;
    float* s_un   = smem + OFF_UN;
    float* Wc     = s_un;              // [32][96] = 3072
    float* s_pc   = s_un + 3072;       // [32][32] = 1024 (vv P chunk)

    const int tid  = threadIdx.x;
    const int wid  = tid >> 5;         // 0..3
    const int lane = tid & 31;
    const int e8   = 8 * wid;          // warp owns edges e8..e8+7
    const int e0g  = blockIdx.x * TE;

    // ---- stage edge features (scalars transposed) ----
    for (int idx = tid; idx < TE * 160; idx += NT) {
        int e = idx / 160;
        int c = idx - e * 160;
        float v1 = fea_in1[e0g * 160 + idx];
        float v2 = fea_in2[e0g * 160 + idx];
        if (c < 64) { s_x1sT[c * 36 + e] = v1; s_x2sT[c * 36 + e] = v2; }
        else        { s_x1v[e * 97 + (c - 64)] = v1; s_x2v[e * 97 + (c - 64)] = v2; }
    }

    // ---- MLP in 2 passes of 16 edges (fw @un[0], h1 in s_sig, h2 @un[2048]) ----
    for (int p = 0; p < 2; p++) {
        const int eb0 = p * 16;
        __syncthreads();
        for (int idx = tid; idx < 16 * 128; idx += NT)
            s_un[idx] = fea_weight[(e0g + eb0) * 128 + idx];
        __syncthreads();
        for (int o = tid; o < 16 * 64; o += NT) {
            int e = o >> 6, j = o & 63;
            float acc = fb1[j];
            const float* xe = s_un + e * 128;
            #pragma unroll 8
            for (int k = 0; k < 128; k++) acc += xe[k] * fw1[k * 64 + j];
            s_sig[o] = acc * sigmoidf_(acc);
        }
        __syncthreads();
        for (int o = tid; o < 16 * 64; o += NT) {
            int e = o >> 6, j = o & 63;
            float acc = fb2[j];
            const float* xe = s_sig + e * 64;
            #pragma unroll 8
            for (int k = 0; k < 64; k++) acc += xe[k] * fw2[k * 64 + j];
            s_un[2048 + o] = acc * sigmoidf_(acc);
        }
        __syncthreads();
        for (int o = tid; o < 16 * 96; o += NT) {
            int e = o / 96, j = o - e * 96;
            float acc = fb3[j];
            const float* xe = s_un + 2048 + e * 64;
            #pragma unroll 8
            for (int k = 0; k < 64; k++) acc += xe[k] * fw3[k * 96 + j];
            s_wout[(eb0 + e) * 96 + j] = acc;
        }
    }

    // ---- main GEMM: [sc|g](e,0:96) over K=5120, 160 chunks of 32 ----
    // accP[pr][col]: pr = edge pair (e8+2pr, e8+2pr+1); col = {lane, lane+32, g lane}
    u64t accP[4][3];
    #pragma unroll
    for (int pr = 0; pr < 4; pr++)
        #pragma unroll
        for (int c = 0; c < 3; c++) accP[pr][c] = 0ull;

    // prefetch W chunk 0 into registers
    float4 wsreg[4], wgreg[2];
    {
        const float* srcS = wsss;
        const float* srcG = wssg;
        #pragma unroll
        for (int i = 0; i < 4; i++) {
            int idx = tid + NT * i; int row = idx >> 4, c4 = idx & 15;
            wsreg[i] = *(const float4*)(srcS + row * 64 + c4 * 4);
        }
        #pragma unroll
        for (int i = 0; i < 2; i++) {
            int idx = tid + NT * i; int row = idx >> 3, c4 = idx & 7;
            wgreg[i] = *(const float4*)(srcG + row * 32 + c4 * 4);
        }
    }

    for (int ci = 0; ci < NCH; ci++) {
        __syncthreads();   // prior chunk's consumers done with Wc / s_pc
        // store current chunk's W
        #pragma unroll
        for (int i = 0; i < 4; i++) {
            int idx = tid + NT * i; int row = idx >> 4, c4 = idx & 15;
            *(float4*)(Wc + row * 96 + c4 * 4) = wsreg[i];
        }
        #pragma unroll
        for (int i = 0; i < 2; i++) {
            int idx = tid + NT * i; int row = idx >> 3, c4 = idx & 7;
            *(float4*)(Wc + row * 96 + 64 + c4 * 4) = wgreg[i];
        }
        // prefetch next chunk's W (lands during compute below)
        if (ci + 1 < NCH) {
            const int cj = ci + 1;
            const float* nS = (cj < 128) ? (wsss + cj * 2048) : (wvvs + (cj - 128) * 2048);
            const float* nG = (cj < 128) ? (wssg + cj * 1024) : (wvvg + (cj - 128) * 1024);
            #pragma unroll
            for (int i = 0; i < 4; i++) {
                int idx = tid + NT * i; int row = idx >> 4, c4 = idx & 15;
                wsreg[i] = *(const float4*)(nS + row * 64 + c4 * 4);
            }
            #pragma unroll
            for (int i = 0; i < 2; i++) {
                int idx = tid + NT * i; int row = idx >> 3, c4 = idx & 7;
                wgreg[i] = *(const float4*)(nG + row * 32 + c4 * 4);
            }
        }
        // vv region: stage P chunk (u fixed = ci-128, kk = v)
        if (ci >= 128) {
            const int u = ci - 128;
            #pragma unroll
            for (int i = 0; i < 8; i++) {
                int idx = tid + NT * i;
                int kk = idx >> 5, e = idx & 31;
                const float* av = s_x1v + e * 97 + u * 3;
                const float* bv = s_x2v + e * 97 + kk * 3;
                s_pc[kk * 32 + e] =
                    INV_SQRT3_F * (av[0] * bv[0] + av[1] * bv[1] + av[2] * bv[2]);
            }
        }
        __syncthreads();

        if (ci < 128) {
            // ss: u fixed per chunk -> factor x1s[u] out of the kk-sum
            const int u  = ci >> 1;
            const int v0 = (ci & 1) * KC;
            const float* xp = s_x2sT + v0 * 36 + e8;
            u64t p[4][3];
            #pragma unroll
            for (int pr = 0; pr < 4; pr++)
                #pragma unroll
                for (int c = 0; c < 3; c++) p[pr][c] = 0ull;
            #pragma unroll 8
            for (int kk = 0; kk < KC; kk++) {
                ulonglong2 x0 = *(const ulonglong2*)(xp + kk * 36);       // edges e8..e8+3
                ulonglong2 x1 = *(const ulonglong2*)(xp + kk * 36 + 4);   // edges e8+4..e8+7
                u64t w0 = splat2(Wc[kk * 96 + lane]);
                u64t w1 = splat2(Wc[kk * 96 + 32 + lane]);
                u64t w2 = splat2(Wc[kk * 96 + 64 + lane]);
                fma2(p[0][0], x0.x, w0); fma2(p[0][1], x0.x, w1); fma2(p[0][2], x0.x, w2);
                fma2(p[1][0], x0.y, w0); fma2(p[1][1], x0.y, w1); fma2(p[1][2], x0.y, w2);
                fma2(p[2][0], x1.x, w0); fma2(p[2][1], x1.x, w1); fma2(p[2][2], x1.x, w2);
                fma2(p[3][0], x1.y, w0); fma2(p[3][1], x1.y, w1); fma2(p[3][2], x1.y, w2);
            }
            ulonglong2 A0 = *(const ulonglong2*)(s_x1sT + u * 36 + e8);
            ulonglong2 A1 = *(const ulonglong2*)(s_x1sT + u * 36 + e8 + 4);
            #pragma unroll
            for (int c = 0; c < 3; c++) {
                fma2(accP[0][c], p[0][c], A0.x);
                fma2(accP[1][c], p[1][c], A0.y);
                fma2(accP[2][c], p[2][c], A1.x);
                fma2(accP[3][c], p[3][c], A1.y);
            }
        } else {
            const float* pp = s_pc + e8;
            #pragma unroll 8
            for (int kk = 0; kk < KC; kk++) {
                ulonglong2 x0 = *(const ulonglong2*)(pp + kk * 32);
                ulonglong2 x1 = *(const ulonglong2*)(pp + kk * 32 + 4);
                u64t w0 = splat2(Wc[kk * 96 + lane]);
                u64t w1 = splat2(Wc[kk * 96 + 32 + lane]);
                u64t w2 = splat2(Wc[kk * 96 + 64 + lane]);
                fma2(accP[0][0], x0.x, w0); fma2(accP[0][1], x0.x, w1); fma2(accP[0][2], x0.x, w2);
                fma2(accP[1][0], x0.y, w0); fma2(accP[1][1], x0.y, w1); fma2(accP[1][2], x0.y, w2);
                fma2(accP[2][0], x1.x, w0); fma2(accP[2][1], x1.x, w1); fma2(accP[2][2], x1.x, w2);
                fma2(accP[3][0], x1.y, w0); fma2(accP[3][1], x1.y, w1); fma2(accP[3][2], x1.y, w2);
            }
        }
    }

    // ---- sc/g epilogue ----
    #pragma unroll
    for (int pr = 0; pr < 4; pr++) {
        float2 c0 = unpack2(accP[pr][0]);
        float2 c1 = unpack2(accP[pr][1]);
        float2 c2 = unpack2(accP[pr][2]);
        #pragma unroll
        for (int h = 0; h < 2; h++) {
            int e = e8 + 2 * pr + h;
            long base = (long)(e0g + e) * 160;
            float a0 = h ? c0.y : c0.x;
            float a1 = h ? c1.y : c1.x;
            float a2 = h ? c2.y : c2.x;
            float s;
            s = A_SC_F * a0;
            out[base + lane] = s * sigmoidf_(s) * s_wout[e * 96 + lane];
            s = A_SC_F * a1;
            out[base + lane + 32] = s * sigmoidf_(s) * s_wout[e * 96 + lane + 32];
            s_sig[e * 32 + lane] = sigmoidf_(A_SC_F * a2);
        }
    }

    // ---- vec: factored GEMMs, 8 edges/warp, register-prefetched staging ----
    float vA[8][3];
    #pragma unroll
    for (int j = 0; j < 8; j++)
        #pragma unroll
        for (int c = 0; c < 3; c++) vA[j][c] = 0.f;

    float4 vreg[8];
    // prefetch sv chunk 0: rows r = u*2+vv -> wsvv[u][v0+vv][.]
    #pragma unroll
    for (int i = 0; i < 8; i++) {
        int idx = tid + NT * i; int r = idx >> 3, c4 = idx & 7;
        vreg[i] = *(const float4*)(wsvv + (r >> 1) * 1024 + (r & 1) * 32 + c4 * 4);
    }

    // sv:  B1[e,v,w] = sum_u x1s[e,u]*wsvv[u,v,w];  vec += B1 * x2v[e,v,i]
    for (int vc = 0; vc < 16; vc++) {
        __syncthreads();
        #pragma unroll
        for (int i = 0; i < 8; i++) {
            int idx = tid + NT * i; int r = idx >> 3, c4 = idx & 7;
            *(float4*)(s_un + r * 32 + c4 * 4) = vreg[i];
        }
        // prefetch next sv chunk, or first vs chunk
        if (vc + 1 < 16) {
            int v0 = (vc + 1) * 2;
            #pragma unroll
            for (int i = 0; i < 8; i++) {
                int idx = tid + NT * i; int r = idx >> 3, c4 = idx & 7;
                vreg[i] = *(const float4*)(wsvv + (r >> 1) * 1024 + (v0 + (r & 1)) * 32 + c4 * 4);
            }
        } else {
            #pragma unroll
            for (int i = 0; i < 8; i++) {
                int idx = tid + NT * i; int r = idx >> 3, c4 = idx & 7;
                vreg[i] = *(const float4*)(wvsv + (r >> 6) * 2048 + (r & 63) * 32 + c4 * 4);
            }
        }
        __syncthreads();

        int v0 = vc * 2;
        u64t b0p[4] = {0ull, 0ull, 0ull, 0ull};
        u64t b1p[4] = {0ull, 0ull, 0ull, 0ull};
        const float* wv = s_un + lane;
        #pragma unroll 8
        for (int u = 0; u < 64; u++) {
            ulonglong2 x0 = *(const ulonglong2*)(s_x1sT + u * 36 + e8);
            ulonglong2 x1 = *(const ulonglong2*)(s_x1sT + u * 36 + e8 + 4);
            u64t w0 = splat2(wv[(u * 2 + 0) * 32]);
            u64t w1 = splat2(wv[(u * 2 + 1) * 32]);
            fma2(b0p[0], x0.x, w0); fma2(b0p[1], x0.y, w0);
            fma2(b0p[2], x1.x, w0); fma2(b0p[3], x1.y, w0);
            fma2(b1p[0], x0.x, w1); fma2(b1p[1], x0.y, w1);
            fma2(b1p[2], x1.x, w1); fma2(b1p[3], x1.y, w1);
        }
        float B0[8], B1[8];
        #pragma unroll
        for (int k2 = 0; k2 < 4; k2++) {
            float2 f = unpack2(b0p[k2]); B0[2 * k2] = f.x; B0[2 * k2 + 1] = f.y;
            float2 g = unpack2(b1p[k2]); B1[2 * k2] = g.x; B1[2 * k2 + 1] = g.y;
        }
        #pragma unroll
        for (int j = 0; j < 8; j++) {
            const float* xv = s_x2v + (e8 + j) * 97 + v0 * 3;
            vA[j][0] += B0[j] * xv[0] + B1[j] * xv[3];
            vA[j][1] += B0[j] * xv[1] + B1[j] * xv[4];
            vA[j][2] += B0[j] * xv[2] + B1[j] * xv[5];
        }
    }

    // vs:  B2[e,u,w] = sum_v x2s[e,v]*wvsv[u,v,w];  vec += B2 * x1v[e,u,i]
    for (int uc = 0; uc < 16; uc++) {
        __syncthreads();
        #pragma unroll
        for (int i = 0; i < 8; i++) {
            int idx = tid + NT * i; int r = idx >> 3, c4 = idx & 7;
            *(float4*)(s_un + r * 32 + c4 * 4) = vreg[i];
        }
        if (uc + 1 < 16) {
            int u0 = (uc + 1) * 2;
            #pragma unroll
            for (int i = 0; i < 8; i++) {
                int idx = tid + NT * i; int r = idx >> 3, c4 = idx & 7;
                vreg[i] = *(const float4*)(wvsv + (u0 + (r >> 6)) * 2048 + (r & 63) * 32 + c4 * 4);
            }
        }
        __syncthreads();

        int u0 = uc * 2;
        u64t b0p[4] = {0ull, 0ull, 0ull, 0ull};
        u64t b1p[4] = {0ull, 0ull, 0ull, 0ull};
        const float* wv = s_un + lane;
        #pragma unroll 8
        for (int v = 0; v < 64; v++) {
            ulonglong2 x0 = *(const ulonglong2*)(s_x2sT + v * 36 + e8);
            ulonglong2 x1 = *(const ulonglong2*)(s_x2sT + v * 36 + e8 + 4);
            u64t w0 = splat2(wv[v * 32]);
            u64t w1 = splat2(wv[(64 + v) * 32]);
            fma2(b0p[0], x0.x, w0); fma2(b0p[1], x0.y, w0);
            fma2(b0p[2], x1.x, w0); fma2(b0p[3], x1.y, w0);
            fma2(b1p[0], x0.x, w1); fma2(b1p[1], x0.y, w1);
            fma2(b1p[2], x1.x, w1); fma2(b1p[3], x1.y, w1);
        }
        float B0[8], B1[8];
        #pragma unroll
        for (int k2 = 0; k2 < 4; k2++) {
            float2 f = unpack2(b0p[k2]); B0[2 * k2] = f.x; B0[2 * k2 + 1] = f.y;
            float2 g = unpack2(b1p[k2]); B1[2 * k2] = g.x; B1[2 * k2 + 1] = g.y;
        }
        #pragma unroll
        for (int j = 0; j < 8; j++) {
            const float* xv = s_x1v + (e8 + j) * 97 + u0 * 3;
            vA[j][0] += B0[j] * xv[0] + B1[j] * xv[3];
            vA[j][1] += B0[j] * xv[1] + B1[j] * xv[4];
            vA[j][2] += B0[j] * xv[2] + B1[j] * xv[5];
        }
    }

    // ---- vec epilogue ----
    #pragma unroll
    for (int j = 0; j < 8; j++) {
        int e = e8 + j;
        float m = A_VEC_F * s_sig[e * 32 + lane] * s_wout[e * 96 + 64 + lane];
        float* o = out + (long)(e0g + e) * 160 + 64 + lane * 3;
        o[0] = vA[j][0] * m;
        o[1] = vA[j][1] * m;
        o[2] = vA[j][2] * m;
    }
}

extern "C" void kernel_launch(void* const* d_in, const int* in_sizes, int n_in,
                              void* d_out, int out_size) {
    (void)in_sizes; (void)n_in; (void)out_size;
    const float* fea_in1    = (const float*)d_in[0];
    const float* fea_in2    = (const float*)d_in[1];
    const float* fea_weight = (const float*)d_in[2];
    const float* w_ss_s     = (const float*)d_in[3];
    const float* w_vv_s     = (const float*)d_in[4];
    const float* w_ss_g     = (const float*)d_in[5];
    const float* w_vv_g     = (const float*)d_in[6];
    const float* w_sv_v     = (const float*)d_in[7];
    const float* w_vs_v     = (const float*)d_in[8];
    const float* fc_w1      = (const float*)d_in[9];
    const float* fc_b1      = (const float*)d_in[10];
    const float* fc_w2      = (const float*)d_in[11];
    const float* fc_b2      = (const float*)d_in[12];
    const float* fc_w3      = (const float*)d_in[13];
    const float* fc_b3      = (const float*)d_in[14];
    float* out = (float*)d_out;

    cudaFuncSetAttribute(equiconv_kernel,
                         cudaFuncAttributeMaxDynamicSharedMemorySize,
                         SMEM_FLOATS * sizeof(float));
    cudaFuncSetAttribute(equiconv_kernel,
                         cudaFuncAttributePreferredSharedMemoryCarveout,
                         cudaSharedmemCarveoutMaxShared);

    const int E = 20000;
    dim3 grid(E / TE);
    dim3 block(NT);
    equiconv_kernel<<<grid, block, SMEM_FLOATS * sizeof(float)>>>(
        fea_in1, fea_in2, fea_weight,
        w_ss_s, w_vv_s, w_ss_g, w_vv_g, w_sv_v, w_vs_v,
        fc_w1, fc_b1, fc_w2, fc_b2, fc_w3, fc_b3,
        out);
}

// round 15
// speedup vs baseline: 1.0650x; 1.0650x over previous
#include <cuda_runtime.h>
#include <cuda_bf16.h>

// EquiConv: main sc/g contraction via warp-level mma.sync m16n8k16 bf16
// (hi/lo compensated split); MLP + vec phase fp32/f32x2.
// TE=64 edges/block, NT=256 (8 warps), grid=313.
#define E_TOT 20000
#define TE 64
#define NT 256
#define NCHK 160   // 128 ss + 32 vv chunks of K=32

#define INV_SQRT3_F 0.5773502691896258f
#define A_SC_F 0.013975424859373686f
#define A_VEC_F 0.015625f

// shared layout (float offsets)
#define OFF_X1ST 0        // [64][68] transposed x1s
#define OFF_X2ST 4352     // [64][68]
#define OFF_X1V  8704     // [64][96]
#define OFF_X2V  14848    // [64][96]
#define OFF_UN   20992    // 6144 union: MLP / Bpack(3328) / Dbuf(6144) / vec(4096)
#define SMEM_FLOATS 27136 // 108544 B -> 2 blocks/SM

typedef unsigned long long u64t;
typedef unsigned int u32t;

__device__ __forceinline__ float sigmoidf_(float x) {
    return __fdividef(1.0f, 1.0f + __expf(-x));
}
__device__ __forceinline__ u64t splat2(float w) {
    u64t r; u32t wi = __float_as_uint(w);
    asm("mov.b64 %0, {%1, %1};" : "=l"(r) : "r"(wi));
    return r;
}
__device__ __forceinline__ void fma2(u64t& d, u64t a, u64t b) {
    asm("fma.rn.f32x2 %0, %1, %2, %0;" : "+l"(d) : "l"(a), "l"(b));
}
__device__ __forceinline__ float2 unpack2(u64t v) {
    u32t lo, hi;
    asm("mov.b64 {%0, %1}, %2;" : "=r"(lo), "=r"(hi) : "l"(v));
    return make_float2(__uint_as_float(lo), __uint_as_float(hi));
}
// split (f0,f1) into packed bf16x2 hi and residual lo (f0 -> low 16 bits)
__device__ __forceinline__ void pack_split(float f0, float f1, u32t& hi, u32t& lo) {
    __nv_bfloat162 h = __float22bfloat162_rn(make_float2(f0, f1));
    float2 hf = __bfloat1622float2(h);
    __nv_bfloat162 l = __float22bfloat162_rn(make_float2(f0 - hf.x, f1 - hf.y));
    hi = *reinterpret_cast<u32t*>(&h);
    lo = *reinterpret_cast<u32t*>(&l);
}
// D += A(16x16 bf16, row) * B(16x8 bf16, col), f32 accumulate
__device__ __forceinline__ void mma_bf16(float& c0, float& c1, float& c2, float& c3,
                                         u32t a0, u32t a1, u32t a2, u32t a3,
                                         u32t b0, u32t b1) {
    asm volatile(
        "mma.sync.aligned.m16n8k16.row.col.f32.bf16.bf16.f32 "
        "{%0,%1,%2,%3}, {%4,%5,%6,%7}, {%8,%9}, {%0,%1,%2,%3};"
        : "+f"(c0), "+f"(c1), "+f"(c2), "+f"(c3)
        : "r"(a0), "r"(a1), "r"(a2), "r"(a3), "r"(b0), "r"(b1));
}

__global__ __launch_bounds__(NT, 2) void equiconv_kernel(
    const float* __restrict__ fea_in1, const float* __restrict__ fea_in2,
    const float* __restrict__ fea_weight,
    const float* __restrict__ wsss, const float* __restrict__ wvvs,
    const float* __restrict__ wssg, const float* __restrict__ wvvg,
    const float* __restrict__ wsvv, const float* __restrict__ wvsv,
    const float* __restrict__ fw1, const float* __restrict__ fb1,
    const float* __restrict__ fw2, const float* __restrict__ fb2,
    const float* __restrict__ fw3, const float* __restrict__ fb3,
    float* __restrict__ out)
{
    extern __shared__ float smem[];
    float* s_x1sT = smem + OFF_X1ST;
    float* s_x2sT = smem + OFF_X2ST;
    float* s_x1v  = smem + OFF_X1V;
    float* s_x2v  = smem + OFF_X2V;
    float* s_un   = smem + OFF_UN;

    const int tid  = threadIdx.x;
    const int wid  = tid >> 5;          // 0..7
    const int lane = tid & 31;
    const int qid  = lane >> 2;         // 0..7
    const int qtr  = lane & 3;          // 0..3
    const int mstrip = wid & 3;         // M strip (16 edges)
    const int nhalf  = wid >> 2;        // N half (48 cols)
    const int em   = mstrip * 16 + qid; // A/C fragment row (edge)
    const int e8   = 8 * wid;           // vec phase: warp owns edges e8..e8+7
    const int e0g  = blockIdx.x * TE;

    // ---- stage edge features ----
    for (int idx = tid; idx < TE * 160; idx += NT) {
        int e = idx / 160, c = idx - e * 160;
        int gE = e0g + e;
        float v1 = 0.f, v2 = 0.f;
        if (gE < E_TOT) { v1 = fea_in1[(long)gE * 160 + c]; v2 = fea_in2[(long)gE * 160 + c]; }
        if (c < 64) { s_x1sT[c * 68 + e] = v1; s_x2sT[c * 68 + e] = v2; }
        else        { s_x1v[e * 96 + (c - 64)] = v1; s_x2v[e * 96 + (c - 64)] = v2; }
    }

    // ---- MLP: 4 passes of 16 edges; wout -> registers ----
    float wr0[8], wr1[8], wr2[8], sgr[8];
    for (int p = 0; p < 4; p++) {
        const int eb0 = p * 16;
        __syncthreads();
        for (int idx = tid; idx < 16 * 128; idx += NT) {
            int e = idx >> 7, gE = e0g + eb0 + e;
            s_un[idx] = (gE < E_TOT) ? fea_weight[(long)gE * 128 + (idx & 127)] : 0.f;
        }
        __syncthreads();
        for (int o = tid; o < 16 * 64; o += NT) {      // h1 @2048
            int e = o >> 6, j = o & 63;
            float acc = fb1[j];
            const float* xe = s_un + e * 128;
            #pragma unroll 8
            for (int k = 0; k < 128; k++) acc += xe[k] * fw1[k * 64 + j];
            s_un[2048 + o] = acc * sigmoidf_(acc);
        }
        __syncthreads();
        for (int o = tid; o < 16 * 64; o += NT) {      // h2 @3072
            int e = o >> 6, j = o & 63;
            float acc = fb2[j];
            const float* xe = s_un + 2048 + e * 64;
            #pragma unroll 8
            for (int k = 0; k < 64; k++) acc += xe[k] * fw2[k * 64 + j];
            s_un[3072 + o] = acc * sigmoidf_(acc);
        }
        __syncthreads();
        for (int o = tid; o < 16 * 96; o += NT) {      // w3 @4096
            int e = o / 96, j = o - e * 96;
            float acc = fb3[j];
            const float* xe = s_un + 3072 + e * 64;
            #pragma unroll 8
            for (int k = 0; k < 64; k++) acc += xe[k] * fw3[k * 96 + j];
            s_un[4096 + o] = acc;
        }
        __syncthreads();
        if ((wid >> 1) == p) {
            #pragma unroll
            for (int j = 0; j < 8; j++) {
                int el = e8 - eb0 + j;
                wr0[j] = s_un[4096 + el * 96 + lane];
                wr1[j] = s_un[4096 + el * 96 + 32 + lane];
                wr2[j] = s_un[4096 + el * 96 + 64 + lane];
            }
        }
    }

    // ---- main GEMM: D[64][96] = P[64][5120] @ Wcat ----
    // acc[nt][0..3]: n-tile nt, fragment regs; thread covers rows em, em+8.
    float acc[6][4];
    #pragma unroll
    for (int nt = 0; nt < 6; nt++)
        #pragma unroll
        for (int c = 0; c < 4; c++) acc[nt][c] = 0.f;

    u32t* Bhi = (u32t*)s_un;          // [16 k2][104]
    u32t* Blo = (u32t*)s_un + 1664;   // [16 k2][104]

    for (int ci = 0; ci < NCHK; ci++) {
        __syncthreads();
        // ---- stage Wcat chunk [32k][96n] as packed bf16-pair hi/lo ----
        const bool ssr = (ci < 128);
        const float* baseS = ssr ? (wsss + ci * 2048) : (wvvs + (ci - 128) * 2048);
        const float* baseG = ssr ? (wssg + ci * 1024) : (wvvg + (ci - 128) * 1024);
        #pragma unroll
        for (int i = 0; i < 6; i++) {
            int idx = tid + NT * i;                    // 1536 pack units
            int k2 = idx / 96, n = idx - k2 * 96;
            float f0, f1;
            if (n < 64) { f0 = baseS[(2 * k2) * 64 + n];        f1 = baseS[(2 * k2 + 1) * 64 + n]; }
            else        { f0 = baseG[(2 * k2) * 32 + (n - 64)]; f1 = baseG[(2 * k2 + 1) * 32 + (n - 64)]; }
            u32t h, l;
            pack_split(f0, f1, h, l);
            Bhi[k2 * 104 + n] = h;
            Blo[k2 * 104 + n] = l;
        }
        __syncthreads();

        // ---- 2 k-steps of 16 ----
        #pragma unroll
        for (int ks = 0; ks < 2; ks++) {
            // build A fragment (P hi/lo)
            u32t a0h, a1h, a2h, a3h, a0l, a1l, a2l, a3l;
            if (ssr) {
                const int u  = ci >> 1;
                const int v0 = (ci & 1) * 32 + ks * 16 + qtr * 2;
                float x1a = s_x1sT[u * 68 + em];
                float x1b = s_x1sT[u * 68 + em + 8];
                float ya0 = s_x2sT[(v0    ) * 68 + em], ya1 = s_x2sT[(v0 + 1) * 68 + em];
                float ya8 = s_x2sT[(v0 + 8) * 68 + em], ya9 = s_x2sT[(v0 + 9) * 68 + em];
                float yb0 = s_x2sT[(v0    ) * 68 + em + 8], yb1 = s_x2sT[(v0 + 1) * 68 + em + 8];
                float yb8 = s_x2sT[(v0 + 8) * 68 + em + 8], yb9 = s_x2sT[(v0 + 9) * 68 + em + 8];
                pack_split(x1a * ya0, x1a * ya1, a0h, a0l);
                pack_split(x1b * yb0, x1b * yb1, a1h, a1l);
                pack_split(x1a * ya8, x1a * ya9, a2h, a2l);
                pack_split(x1b * yb8, x1b * yb9, a3h, a3l);
            } else {
                const int u  = ci - 128;
                const int v0 = ks * 16 + qtr * 2;
                const float* va = s_x1v + em * 96 + u * 3;
                const float* vb = s_x1v + (em + 8) * 96 + u * 3;
                float p[8];
                #pragma unroll
                for (int q = 0; q < 4; q++) {
                    int v = v0 + (q & 1) + (q >> 1) * 8;    // v0, v0+1, v0+8, v0+9
                    const float* wa = s_x2v + em * 96 + v * 3;
                    const float* wb = s_x2v + (em + 8) * 96 + v * 3;
                    p[q]     = INV_SQRT3_F * (va[0] * wa[0] + va[1] * wa[1] + va[2] * wa[2]);
                    p[4 + q] = INV_SQRT3_F * (vb[0] * wb[0] + vb[1] * wb[1] + vb[2] * wb[2]);
                }
                pack_split(p[0], p[1], a0h, a0l);
                pack_split(p[4], p[5], a1h, a1l);
                pack_split(p[2], p[3], a2h, a2l);
                pack_split(p[6], p[7], a3h, a3l);
            }
            // 6 n-tiles x (hi*hi + hi*lo + lo*hi)
            #pragma unroll
            for (int nt = 0; nt < 6; nt++) {
                int n = nhalf * 48 + nt * 8 + qid;
                u32t bh0 = Bhi[(ks * 8 + qtr) * 104 + n];
                u32t bh1 = Bhi[(ks * 8 + qtr + 4) * 104 + n];
                u32t bl0 = Blo[(ks * 8 + qtr) * 104 + n];
                u32t bl1 = Blo[(ks * 8 + qtr + 4) * 104 + n];
                mma_bf16(acc[nt][0], acc[nt][1], acc[nt][2], acc[nt][3],
                         a0h, a1h, a2h, a3h, bh0, bh1);
                mma_bf16(acc[nt][0], acc[nt][1], acc[nt][2], acc[nt][3],
                         a0h, a1h, a2h, a3h, bl0, bl1);
                mma_bf16(acc[nt][0], acc[nt][1], acc[nt][2], acc[nt][3],
                         a0l, a1l, a2l, a3l, bh0, bh1);
            }
        }
    }

    // ---- write D fragments to smem, then sc/g epilogue ----
    __syncthreads();
    float* Dbuf = s_un;   // [64][96]
    #pragma unroll
    for (int nt = 0; nt < 6; nt++) {
        int n = nhalf * 48 + nt * 8 + qtr * 2;
        *(float2*)(Dbuf + em * 96 + n)       = make_float2(acc[nt][0], acc[nt][1]);
        *(float2*)(Dbuf + (em + 8) * 96 + n) = make_float2(acc[nt][2], acc[nt][3]);
    }
    __syncthreads();
    #pragma unroll
    for (int j = 0; j < 8; j++) {
        int e = e8 + j, gE = e0g + e;
        float s0 = A_SC_F * Dbuf[e * 96 + lane];
        float s1 = A_SC_F * Dbuf[e * 96 + 32 + lane];
        sgr[j] = sigmoidf_(A_SC_F * Dbuf[e * 96 + 64 + lane]);
        if (gE < E_TOT) {
            long base = (long)gE * 160;
            out[base + lane]      = s0 * sigmoidf_(s0) * wr0[j];
            out[base + lane + 32] = s1 * sigmoidf_(s1) * wr1[j];
        }
    }

    // ---- vec phase: fp32 factored GEMMs, 8 edges/warp, f32x2 ----
    float vA[8][3];
    #pragma unroll
    for (int j = 0; j < 8; j++)
        #pragma unroll
        for (int c = 0; c < 3; c++) vA[j][c] = 0.f;

    // sv: B1[e,v,w] = sum_u x1s[e,u]*wsvv[u,v,w]; vec += B1 * x2v[e,v,i]
    for (int vc = 0; vc < 16; vc++) {
        __syncthreads();
        int v0 = vc * 2;
        #pragma unroll
        for (int i = 0; i < 4; i++) {
            int fidx = tid + NT * i;          // 1024 float4 = [128 rows][32]
            int r = fidx >> 3, c4 = fidx & 7;
            *(float4*)(s_un + r * 32 + c4 * 4) =
                *(const float4*)(wsvv + (r >> 1) * 1024 + (v0 + (r & 1)) * 32 + c4 * 4);
        }
        __syncthreads();
        u64t b0p[4] = {0, 0, 0, 0}, b1p[4] = {0, 0, 0, 0};
        const float* wv = s_un + lane;
        #pragma unroll 8
        for (int u = 0; u < 64; u++) {
            ulonglong2 x0 = *(const ulonglong2*)(s_x1sT + u * 68 + e8);
            ulonglong2 x1 = *(const ulonglong2*)(s_x1sT + u * 68 + e8 + 4);
            u64t w0 = splat2(wv[(u * 2 + 0) * 32]);
            u64t w1 = splat2(wv[(u * 2 + 1) * 32]);
            fma2(b0p[0], x0.x, w0); fma2(b0p[1], x0.y, w0);
            fma2(b0p[2], x1.x, w0); fma2(b0p[3], x1.y, w0);
            fma2(b1p[0], x0.x, w1); fma2(b1p[1], x0.y, w1);
            fma2(b1p[2], x1.x, w1); fma2(b1p[3], x1.y, w1);
        }
        float B0[8], B1[8];
        #pragma unroll
        for (int k2 = 0; k2 < 4; k2++) {
            float2 f = unpack2(b0p[k2]); B0[2 * k2] = f.x; B0[2 * k2 + 1] = f.y;
            float2 g = unpack2(b1p[k2]); B1[2 * k2] = g.x; B1[2 * k2 + 1] = g.y;
        }
        #pragma unroll
        for (int j = 0; j < 8; j++) {
            const float* xv = s_x2v + (e8 + j) * 96 + v0 * 3;
            vA[j][0] += B0[j] * xv[0] + B1[j] * xv[3];
            vA[j][1] += B0[j] * xv[1] + B1[j] * xv[4];
            vA[j][2] += B0[j] * xv[2] + B1[j] * xv[5];
        }
    }
    // vs: B2[e,u,w] = sum_v x2s[e,v]*wvsv[u,v,w]; vec += B2 * x1v[e,u,i]
    for (int uc = 0; uc < 16; uc++) {
        __syncthreads();
        int u0 = uc * 2;
        #pragma unroll
        for (int i = 0; i < 4; i++) {
            int fidx = tid + NT * i;          // [128 rows][32]: row = uu*64 + v
            int r = fidx >> 3, c4 = fidx & 7;
            *(float4*)(s_un + r * 32 + c4 * 4) =
                *(const float4*)(wvsv + (u0 + (r >> 6)) * 2048 + (r & 63) * 32 + c4 * 4);
        }
        __syncthreads();
        u64t b0p[4] = {0, 0, 0, 0}, b1p[4] = {0, 0, 0, 0};
        const float* wv = s_un + lane;
        #pragma unroll 8
        for (int v = 0; v < 64; v++) {
            ulonglong2 x0 = *(const ulonglong2*)(s_x2sT + v * 68 + e8);
            ulonglong2 x1 = *(const ulonglong2*)(s_x2sT + v * 68 + e8 + 4);
            u64t w0 = splat2(wv[v * 32]);
            u64t w1 = splat2(wv[(64 + v) * 32]);
            fma2(b0p[0], x0.x, w0); fma2(b0p[1], x0.y, w0);
            fma2(b0p[2], x1.x, w0); fma2(b0p[3], x1.y, w0);
            fma2(b1p[0], x0.x, w1); fma2(b1p[1], x0.y, w1);
            fma2(b1p[2], x1.x, w1); fma2(b1p[3], x1.y, w1);
        }
        float B0[8], B1[8];
        #pragma unroll
        for (int k2 = 0; k2 < 4; k2++) {
            float2 f = unpack2(b0p[k2]); B0[2 * k2] = f.x; B0[2 * k2 + 1] = f.y;
            float2 g = unpack2(b1p[k2]); B1[2 * k2] = g.x; B1[2 * k2 + 1] = g.y;
        }
        #pragma unroll
        for (int j = 0; j < 8; j++) {
            const float* xv = s_x1v + (e8 + j) * 96 + u0 * 3;
            vA[j][0] += B0[j] * xv[0] + B1[j] * xv[3];
            vA[j][1] += B0[j] * xv[1] + B1[j] * xv[4];
            vA[j][2] += B0[j] * xv[2] + B1[j] * xv[5];
        }
    }
    #pragma unroll
    for (int j = 0; j < 8; j++) {
        int gE = e0g + e8 + j;
        if (gE < E_TOT) {
            float m = A_VEC_F * sgr[j] * wr2[j];
            float* o = out + (long)gE * 160 + 64 + lane * 3;
            o[0] = vA[j][0] * m;
            o[1] = vA[j][1] * m;
            o[2] = vA[j][2] * m;
        }
    }
}

extern "C" void kernel_launch(void* const* d_in, const int* in_sizes, int n_in,
                              void* d_out, int out_size) {
    (void)in_sizes; (void)n_in; (void)out_size;
    const float* fea_in1    = (const float*)d_in[0];
    const float* fea_in2    = (const float*)d_in[1];
    const float* fea_weight = (const float*)d_in[2];
    const float* w_ss_s     = (const float*)d_in[3];
    const float* w_vv_s     = (const float*)d_in[4];
    const float* w_ss_g     = (const float*)d_in[5];
    const float* w_vv_g     = (const float*)d_in[6];
    const float* w_sv_v     = (const float*)d_in[7];
    const float* w_vs_v     = (const float*)d_in[8];
    const float* fc_w1      = (const float*)d_in[9];
    const float* fc_b1      = (const float*)d_in[10];
    const float* fc_w2      = (const float*)d_in[11];
    const float* fc_b2      = (const float*)d_in[12];
    const float* fc_w3      = (const float*)d_in[13];
    const float* fc_b3      = (const float*)d_in[14];
    float* out = (float*)d_out;

    cudaFuncSetAttribute(equiconv_kernel,
                         cudaFuncAttributeMaxDynamicSharedMemorySize,
                         SMEM_FLOATS * sizeof(float));
    cudaFuncSetAttribute(equiconv_kernel,
                         cudaFuncAttributePreferredSharedMemoryCarveout,
                         cudaSharedmemCarveoutMaxShared);

    dim3 grid((E_TOT + TE - 1) / TE);   // 313
    dim3 block(NT);
    equiconv_kernel<<<grid, block, SMEM_FLOATS * sizeof(float)>>>(
        fea_in1, fea_in2, fea_weight,
        w_ss_s, w_vv_s, w_ss_g, w_vv_g, w_sv_v, w_vs_v,
        fc_w1, fc_b1, fc_w2, fc_b2, fc_w3, fc_b3,
        out);
}

// round 16
// speedup vs baseline: 1.1148x; 1.0468x over previous
#include <cuda_runtime.h>
#include <cuda_bf16.h>

// EquiConv: main sc/g contraction via warp-level mma.sync m16n8k16 bf16
// (hi/lo compensated split) with PREPACKED bf16 weights; MLP + vec fp32/f32x2.
// TE=64 edges/block, NT=256 (8 warps), grid=313. Prepack kernel runs first.
#define E_TOT 20000
#define TE 64
#define NT 256
#define NCHK 160   // 128 ss + 32 vv chunks of K=32
#define CHW 1664   // u32 per chunk per array: [16 k2][104]

#define INV_SQRT3_F 0.5773502691896258f
#define A_SC_F 0.013975424859373686f
#define A_VEC_F 0.015625f

// shared layout (float offsets)
#define OFF_X1ST 0        // [64][68] transposed x1s
#define OFF_X2ST 4352     // [64][68]
#define OFF_X1V  8704     // [64][96]
#define OFF_X2V  14848    // [64][96]
#define OFF_UN   20992    // 6144 union: MLP / Bpack(3328) / Dbuf(6144) / vec(4096)
#define SMEM_FLOATS 27136 // 108544 B -> 2 blocks/SM

typedef unsigned long long u64t;
typedef unsigned int u32t;

// prepacked bf16x2 hi/lo weights, laid out exactly as the per-chunk smem image
__device__ uint4 g_Whi4[NCHK * CHW / 4];
__device__ uint4 g_Wlo4[NCHK * CHW / 4];

__device__ __forceinline__ float sigmoidf_(float x) {
    return __fdividef(1.0f, 1.0f + __expf(-x));
}
__device__ __forceinline__ u64t splat2(float w) {
    u64t r; u32t wi = __float_as_uint(w);
    asm("mov.b64 %0, {%1, %1};" : "=l"(r) : "r"(wi));
    return r;
}
__device__ __forceinline__ void fma2(u64t& d, u64t a, u64t b) {
    asm("fma.rn.f32x2 %0, %1, %2, %0;" : "+l"(d) : "l"(a), "l"(b));
}
__device__ __forceinline__ float2 unpack2(u64t v) {
    u32t lo, hi;
    asm("mov.b64 {%0, %1}, %2;" : "=r"(lo), "=r"(hi) : "l"(v));
    return make_float2(__uint_as_float(lo), __uint_as_float(hi));
}
// split (f0,f1) into packed bf16x2 hi and residual lo (f0 -> low 16 bits)
__device__ __forceinline__ void pack_split(float f0, float f1, u32t& hi, u32t& lo) {
    __nv_bfloat162 h = __float22bfloat162_rn(make_float2(f0, f1));
    float2 hf = __bfloat1622float2(h);
    __nv_bfloat162 l = __float22bfloat162_rn(make_float2(f0 - hf.x, f1 - hf.y));
    hi = *reinterpret_cast<u32t*>(&h);
    lo = *reinterpret_cast<u32t*>(&l);
}
// D += A(16x16 bf16, row) * B(16x8 bf16, col), f32 accumulate
__device__ __forceinline__ void mma_bf16(float& c0, float& c1, float& c2, float& c3,
                                         u32t a0, u32t a1, u32t a2, u32t a3,
                                         u32t b0, u32t b1) {
    asm volatile(
        "mma.sync.aligned.m16n8k16.row.col.f32.bf16.bf16.f32 "
        "{%0,%1,%2,%3}, {%4,%5,%6,%7}, {%8,%9}, {%0,%1,%2,%3};"
        : "+f"(c0), "+f"(c1), "+f"(c2), "+f"(c3)
        : "r"(a0), "r"(a1), "r"(a2), "r"(a3), "r"(b0), "r"(b1));
}

// ---- prepack: fp32 Wcat -> bf16 hi/lo, per-chunk [16][104] image ----
__global__ __launch_bounds__(256) void prepack_kernel(
    const float* __restrict__ wsss, const float* __restrict__ wvvs,
    const float* __restrict__ wssg, const float* __restrict__ wvvg)
{
    const int ci = blockIdx.x;
    const bool ssr = (ci < 128);
    const float* baseS = ssr ? (wsss + ci * 2048) : (wvvs + (ci - 128) * 2048);
    const float* baseG = ssr ? (wssg + ci * 1024) : (wvvg + (ci - 128) * 1024);
    u32t* dH = (u32t*)g_Whi4 + ci * CHW;
    u32t* dL = (u32t*)g_Wlo4 + ci * CHW;
    for (int idx = threadIdx.x; idx < CHW; idx += 256) {
        int k2 = idx / 104, n = idx - k2 * 104;
        u32t h = 0, l = 0;
        if (n < 96) {
            float f0, f1;
            if (n < 64) { f0 = baseS[(2 * k2) * 64 + n];        f1 = baseS[(2 * k2 + 1) * 64 + n]; }
            else        { f0 = baseG[(2 * k2) * 32 + (n - 64)]; f1 = baseG[(2 * k2 + 1) * 32 + (n - 64)]; }
            pack_split(f0, f1, h, l);
        }
        dH[idx] = h;
        dL[idx] = l;
    }
}

__global__ __launch_bounds__(NT, 2) void equiconv_kernel(
    const float* __restrict__ fea_in1, const float* __restrict__ fea_in2,
    const float* __restrict__ fea_weight,
    const float* __restrict__ wsvv, const float* __restrict__ wvsv,
    const float* __restrict__ fw1, const float* __restrict__ fb1,
    const float* __restrict__ fw2, const float* __restrict__ fb2,
    const float* __restrict__ fw3, const float* __restrict__ fb3,
    float* __restrict__ out)
{
    extern __shared__ float smem[];
    float* s_x1sT = smem + OFF_X1ST;
    float* s_x2sT = smem + OFF_X2ST;
    float* s_x1v  = smem + OFF_X1V;
    float* s_x2v  = smem + OFF_X2V;
    float* s_un   = smem + OFF_UN;

    const int tid  = threadIdx.x;
    const int wid  = tid >> 5;          // 0..7
    const int lane = tid & 31;
    const int qid  = lane >> 2;         // 0..7
    const int qtr  = lane & 3;          // 0..3
    const int mstrip = wid & 3;         // M strip (16 edges)
    const int nhalf  = wid >> 2;        // N half (48 cols)
    const int em   = mstrip * 16 + qid; // A/C fragment row (edge)
    const int e8   = 8 * wid;           // vec phase: warp owns edges e8..e8+7
    const int e0g  = blockIdx.x * TE;

    // ---- stage edge features ----
    for (int idx = tid; idx < TE * 160; idx += NT) {
        int e = idx / 160, c = idx - e * 160;
        int gE = e0g + e;
        float v1 = 0.f, v2 = 0.f;
        if (gE < E_TOT) { v1 = fea_in1[(long)gE * 160 + c]; v2 = fea_in2[(long)gE * 160 + c]; }
        if (c < 64) { s_x1sT[c * 68 + e] = v1; s_x2sT[c * 68 + e] = v2; }
        else        { s_x1v[e * 96 + (c - 64)] = v1; s_x2v[e * 96 + (c - 64)] = v2; }
    }

    // ---- MLP: 4 passes of 16 edges; wout -> registers ----
    float wr0[8], wr1[8], wr2[8], sgr[8];
    for (int p = 0; p < 4; p++) {
        const int eb0 = p * 16;
        __syncthreads();
        for (int idx = tid; idx < 16 * 128; idx += NT) {
            int e = idx >> 7, gE = e0g + eb0 + e;
            s_un[idx] = (gE < E_TOT) ? fea_weight[(long)gE * 128 + (idx & 127)] : 0.f;
        }
        __syncthreads();
        for (int o = tid; o < 16 * 64; o += NT) {      // h1 @2048
            int e = o >> 6, j = o & 63;
            float acc = fb1[j];
            const float* xe = s_un + e * 128;
            #pragma unroll 8
            for (int k = 0; k < 128; k++) acc += xe[k] * fw1[k * 64 + j];
            s_un[2048 + o] = acc * sigmoidf_(acc);
        }
        __syncthreads();
        for (int o = tid; o < 16 * 64; o += NT) {      // h2 @3072
            int e = o >> 6, j = o & 63;
            float acc = fb2[j];
            const float* xe = s_un + 2048 + e * 64;
            #pragma unroll 8
            for (int k = 0; k < 64; k++) acc += xe[k] * fw2[k * 64 + j];
            s_un[3072 + o] = acc * sigmoidf_(acc);
        }
        __syncthreads();
        for (int o = tid; o < 16 * 96; o += NT) {      // w3 @4096
            int e = o / 96, j = o - e * 96;
            float acc = fb3[j];
            const float* xe = s_un + 3072 + e * 64;
            #pragma unroll 8
            for (int k = 0; k < 64; k++) acc += xe[k] * fw3[k * 96 + j];
            s_un[4096 + o] = acc;
        }
        __syncthreads();
        if ((wid >> 1) == p) {
            #pragma unroll
            for (int j = 0; j < 8; j++) {
                int el = e8 - eb0 + j;
                wr0[j] = s_un[4096 + el * 96 + lane];
                wr1[j] = s_un[4096 + el * 96 + 32 + lane];
                wr2[j] = s_un[4096 + el * 96 + 64 + lane];
            }
        }
    }

    // ---- main GEMM: D[64][96] = P[64][5120] @ Wcat ----
    float acc[6][4];
    #pragma unroll
    for (int nt = 0; nt < 6; nt++)
        #pragma unroll
        for (int c = 0; c < 4; c++) acc[nt][c] = 0.f;

    u32t* Bhi = (u32t*)s_un;          // [16 k2][104]
    u32t* Blo = (u32t*)s_un + CHW;    // [16 k2][104]

    for (int ci = 0; ci < NCHK; ci++) {
        __syncthreads();
        // ---- stage prepacked W chunk: flat uint4 copy (832 vectors) ----
        const uint4* srcH = g_Whi4 + ci * (CHW / 4);
        const uint4* srcL = g_Wlo4 + ci * (CHW / 4);
        #pragma unroll
        for (int i = 0; i < 4; i++) {
            int idx = tid + NT * i;
            if (idx < 832) {
                if (idx < 416) ((uint4*)Bhi)[idx] = srcH[idx];
                else           ((uint4*)Blo)[idx - 416] = srcL[idx - 416];
            }
        }
        __syncthreads();

        const bool ssr = (ci < 128);
        // ---- 2 k-steps of 16 ----
        #pragma unroll
        for (int ks = 0; ks < 2; ks++) {
            u32t a0h, a1h, a2h, a3h, a0l, a1l, a2l, a3l;
            if (ssr) {
                const int u  = ci >> 1;
                const int v0 = (ci & 1) * 32 + ks * 16 + qtr * 2;
                float x1a = s_x1sT[u * 68 + em];
                float x1b = s_x1sT[u * 68 + em + 8];
                float ya0 = s_x2sT[(v0    ) * 68 + em], ya1 = s_x2sT[(v0 + 1) * 68 + em];
                float ya8 = s_x2sT[(v0 + 8) * 68 + em], ya9 = s_x2sT[(v0 + 9) * 68 + em];
                float yb0 = s_x2sT[(v0    ) * 68 + em + 8], yb1 = s_x2sT[(v0 + 1) * 68 + em + 8];
                float yb8 = s_x2sT[(v0 + 8) * 68 + em + 8], yb9 = s_x2sT[(v0 + 9) * 68 + em + 8];
                pack_split(x1a * ya0, x1a * ya1, a0h, a0l);
                pack_split(x1b * yb0, x1b * yb1, a1h, a1l);
                pack_split(x1a * ya8, x1a * ya9, a2h, a2l);
                pack_split(x1b * yb8, x1b * yb9, a3h, a3l);
            } else {
                const int u  = ci - 128;
                const int v0 = ks * 16 + qtr * 2;
                const float* va = s_x1v + em * 96 + u * 3;
                const float* vb = s_x1v + (em + 8) * 96 + u * 3;
                float p[8];
                #pragma unroll
                for (int q = 0; q < 4; q++) {
                    int v = v0 + (q & 1) + (q >> 1) * 8;    // v0, v0+1, v0+8, v0+9
                    const float* wa = s_x2v + em * 96 + v * 3;
                    const float* wb = s_x2v + (em + 8) * 96 + v * 3;
                    p[q]     = INV_SQRT3_F * (va[0] * wa[0] + va[1] * wa[1] + va[2] * wa[2]);
                    p[4 + q] = INV_SQRT3_F * (vb[0] * wb[0] + vb[1] * wb[1] + vb[2] * wb[2]);
                }
                pack_split(p[0], p[1], a0h, a0l);
                pack_split(p[4], p[5], a1h, a1l);
                pack_split(p[2], p[3], a2h, a2l);
                pack_split(p[6], p[7], a3h, a3l);
            }
            #pragma unroll
            for (int nt = 0; nt < 6; nt++) {
                int n = nhalf * 48 + nt * 8 + qid;
                u32t bh0 = Bhi[(ks * 8 + qtr) * 104 + n];
                u32t bh1 = Bhi[(ks * 8 + qtr + 4) * 104 + n];
                u32t bl0 = Blo[(ks * 8 + qtr) * 104 + n];
                u32t bl1 = Blo[(ks * 8 + qtr + 4) * 104 + n];
                mma_bf16(acc[nt][0], acc[nt][1], acc[nt][2], acc[nt][3],
                         a0h, a1h, a2h, a3h, bh0, bh1);
                mma_bf16(acc[nt][0], acc[nt][1], acc[nt][2], acc[nt][3],
                         a0h, a1h, a2h, a3h, bl0, bl1);
                mma_bf16(acc[nt][0], acc[nt][1], acc[nt][2], acc[nt][3],
                         a0l, a1l, a2l, a3l, bh0, bh1);
            }
        }
    }

    // ---- write D fragments to smem, then sc/g epilogue ----
    __syncthreads();
    float* Dbuf = s_un;   // [64][96]
    #pragma unroll
    for (int nt = 0; nt < 6; nt++) {
        int n = nhalf * 48 + nt * 8 + qtr * 2;
        *(float2*)(Dbuf + em * 96 + n)       = make_float2(acc[nt][0], acc[nt][1]);
        *(float2*)(Dbuf + (em + 8) * 96 + n) = make_float2(acc[nt][2], acc[nt][3]);
    }
    __syncthreads();
    #pragma unroll
    for (int j = 0; j < 8; j++) {
        int e = e8 + j, gE = e0g + e;
        float s0 = A_SC_F * Dbuf[e * 96 + lane];
        float s1 = A_SC_F * Dbuf[e * 96 + 32 + lane];
        sgr[j] = sigmoidf_(A_SC_F * Dbuf[e * 96 + 64 + lane]);
        if (gE < E_TOT) {
            long base = (long)gE * 160;
            out[base + lane]      = s0 * sigmoidf_(s0) * wr0[j];
            out[base + lane + 32] = s1 * sigmoidf_(s1) * wr1[j];
        }
    }

    // ---- vec phase: fp32 factored GEMMs, 8 edges/warp, f32x2 ----
    float vA[8][3];
    #pragma unroll
    for (int j = 0; j < 8; j++)
        #pragma unroll
        for (int c = 0; c < 3; c++) vA[j][c] = 0.f;

    // sv: B1[e,v,w] = sum_u x1s[e,u]*wsvv[u,v,w]; vec += B1 * x2v[e,v,i]
    for (int vc = 0; vc < 16; vc++) {
        __syncthreads();
        int v0 = vc * 2;
        #pragma unroll
        for (int i = 0; i < 4; i++) {
            int fidx = tid + NT * i;          // 1024 float4 = [128 rows][32]
            int r = fidx >> 3, c4 = fidx & 7;
            *(float4*)(s_un + r * 32 + c4 * 4) =
                *(const float4*)(wsvv + (r >> 1) * 1024 + (v0 + (r & 1)) * 32 + c4 * 4);
        }
        __syncthreads();
        u64t b0p[4] = {0, 0, 0, 0}, b1p[4] = {0, 0, 0, 0};
        const float* wv = s_un + lane;
        #pragma unroll 8
        for (int u = 0; u < 64; u++) {
            ulonglong2 x0 = *(const ulonglong2*)(s_x1sT + u * 68 + e8);
            ulonglong2 x1 = *(const ulonglong2*)(s_x1sT + u * 68 + e8 + 4);
            u64t w0 = splat2(wv[(u * 2 + 0) * 32]);
            u64t w1 = splat2(wv[(u * 2 + 1) * 32]);
            fma2(b0p[0], x0.x, w0); fma2(b0p[1], x0.y, w0);
            fma2(b0p[2], x1.x, w0); fma2(b0p[3], x1.y, w0);
            fma2(b1p[0], x0.x, w1); fma2(b1p[1], x0.y, w1);
            fma2(b1p[2], x1.x, w1); fma2(b1p[3], x1.y, w1);
        }
        float B0[8], B1[8];
        #pragma unroll
        for (int k2 = 0; k2 < 4; k2++) {
            float2 f = unpack2(b0p[k2]); B0[2 * k2] = f.x; B0[2 * k2 + 1] = f.y;
            float2 g = unpack2(b1p[k2]); B1[2 * k2] = g.x; B1[2 * k2 + 1] = g.y;
        }
        #pragma unroll
        for (int j = 0; j < 8; j++) {
            const float* xv = s_x2v + (e8 + j) * 96 + v0 * 3;
            vA[j][0] += B0[j] * xv[0] + B1[j] * xv[3];
            vA[j][1] += B0[j] * xv[1] + B1[j] * xv[4];
            vA[j][2] += B0[j] * xv[2] + B1[j] * xv[5];
        }
    }
    // vs: B2[e,u,w] = sum_v x2s[e,v]*wvsv[u,v,w]; vec += B2 * x1v[e,u,i]
    for (int uc = 0; uc < 16; uc++) {
        __syncthreads();
        int u0 = uc * 2;
        #pragma unroll
        for (int i = 0; i < 4; i++) {
            int fidx = tid + NT * i;          // [128 rows][32]: row = uu*64 + v
            int r = fidx >> 3, c4 = fidx & 7;
            *(float4*)(s_un + r * 32 + c4 * 4) =
                *(const float4*)(wvsv + (u0 + (r >> 6)) * 2048 + (r & 63) * 32 + c4 * 4);
        }
        __syncthreads();
        u64t b0p[4] = {0, 0, 0, 0}, b1p[4] = {0, 0, 0, 0};
        const float* wv = s_un + lane;
        #pragma unroll 8
        for (int v = 0; v < 64; v++) {
            ulonglong2 x0 = *(const ulonglong2*)(s_x2sT + v * 68 + e8);
            ulonglong2 x1 = *(const ulonglong2*)(s_x2sT + v * 68 + e8 + 4);
            u64t w0 = splat2(wv[v * 32]);
            u64t w1 = splat2(wv[(64 + v) * 32]);
            fma2(b0p[0], x0.x, w0); fma2(b0p[1], x0.y, w0);
            fma2(b0p[2], x1.x, w0); fma2(b0p[3], x1.y, w0);
            fma2(b1p[0], x0.x, w1); fma2(b1p[1], x0.y, w1);
            fma2(b1p[2], x1.x, w1); fma2(b1p[3], x1.y, w1);
        }
        float B0[8], B1[8];
        #pragma unroll
        for (int k2 = 0; k2 < 4; k2++) {
            float2 f = unpack2(b0p[k2]); B0[2 * k2] = f.x; B0[2 * k2 + 1] = f.y;
            float2 g = unpack2(b1p[k2]); B1[2 * k2] = g.x; B1[2 * k2 + 1] = g.y;
        }
        #pragma unroll
        for (int j = 0; j < 8; j++) {
            const float* xv = s_x1v + (e8 + j) * 96 + u0 * 3;
            vA[j][0] += B0[j] * xv[0] + B1[j] * xv[3];
            vA[j][1] += B0[j] * xv[1] + B1[j] * xv[4];
            vA[j][2] += B0[j] * xv[2] + B1[j] * xv[5];
        }
    }
    #pragma unroll
    for (int j = 0; j < 8; j++) {
        int gE = e0g + e8 + j;
        if (gE < E_TOT) {
            float m = A_VEC_F * sgr[j] * wr2[j];
            float* o = out + (long)gE * 160 + 64 + lane * 3;
            o[0] = vA[j][0] * m;
            o[1] = vA[j][1] * m;
            o[2] = vA[j][2] * m;
        }
    }
}

extern "C" void kernel_launch(void* const* d_in, const int* in_sizes, int n_in,
                              void* d_out, int out_size) {
    (void)in_sizes; (void)n_in; (void)out_size;
    const float* fea_in1    = (const float*)d_in[0];
    const float* fea_in2    = (const float*)d_in[1];
    const float* fea_weight = (const float*)d_in[2];
    const float* w_ss_s     = (const float*)d_in[3];
    const float* w_vv_s     = (const float*)d_in[4];
    const float* w_ss_g     = (const float*)d_in[5];
    const float* w_vv_g     = (const float*)d_in[6];
    const float* w_sv_v     = (const float*)d_in[7];
    const float* w_vs_v     = (const float*)d_in[8];
    const float* fc_w1      = (const float*)d_in[9];
    const float* fc_b1      = (const float*)d_in[10];
    const float* fc_w2      = (const float*)d_in[11];
    const float* fc_b2      = (const float*)d_in[12];
    const float* fc_w3      = (const float*)d_in[13];
    const float* fc_b3      = (const float*)d_in[14];
    float* out = (float*)d_out;

    cudaFuncSetAttribute(equiconv_kernel,
                         cudaFuncAttributeMaxDynamicSharedMemorySize,
                         SMEM_FLOATS * sizeof(float));
    cudaFuncSetAttribute(equiconv_kernel,
                         cudaFuncAttributePreferredSharedMemoryCarveout,
                         cudaSharedmemCarveoutMaxShared);

    prepack_kernel<<<NCHK, 256>>>(w_ss_s, w_vv_s, w_ss_g, w_vv_g);

    dim3 grid((E_TOT + TE - 1) / TE);   // 313
    dim3 block(NT);
    equiconv_kernel<<<grid, block, SMEM_FLOATS * sizeof(float)>>>(
        fea_in1, fea_in2, fea_weight,
        w_sv_v, w_vs_v,
        fc_w1, fc_b1, fc_w2, fc_b2, fc_w3, fc_b3,
        out);
}

// round 17
// speedup vs baseline: 1.2816x; 1.1496x over previous
#include <cuda_runtime.h>
#include <cuda_bf16.h>

// EquiConv: main sc/g contraction via warp-level mma.sync m16n8k16 bf16
// (hi/lo compensated split) with FRAGMENT-ORDERED prepacked weights loaded
// directly per-warp from global (barrier-free main loop).
// TE=64 edges/block, NT=256 (8 warps), grid=313. Prepack kernel runs first.
#define E_TOT 20000
#define TE 64
#define NT 256
#define NCHK 160   // 128 ss + 32 vv chunks of K=32

#define INV_SQRT3_F 0.5773502691896258f
#define A_SC_F 0.013975424859373686f
#define A_VEC_F 0.015625f

// shared layout (float offsets)
#define OFF_X1ST 0        // [64][68] transposed x1s
#define OFF_X2ST 4352     // [64][68]
#define OFF_X1V  8704     // [64][96]
#define OFF_X2V  14848    // [64][96]
#define OFF_UN   20992    // 6144 union: MLP / Dbuf(6144) / vec(4096)
#define SMEM_FLOATS 27136 // 108544 B -> 2 blocks/SM

typedef unsigned long long u64t;
typedef unsigned int u32t;

// fragment-ordered prepacked weights:
// g_Wfrag[ci*768 + ks*384 + n*4 + qtr] = {bh0, bh1, bl0, bl1}
__device__ uint4 g_Wfrag[NCHK * 768];

__device__ __forceinline__ float sigmoidf_(float x) {
    return __fdividef(1.0f, 1.0f + __expf(-x));
}
__device__ __forceinline__ u64t splat2(float w) {
    u64t r; u32t wi = __float_as_uint(w);
    asm("mov.b64 %0, {%1, %1};" : "=l"(r) : "r"(wi));
    return r;
}
__device__ __forceinline__ void fma2(u64t& d, u64t a, u64t b) {
    asm("fma.rn.f32x2 %0, %1, %2, %0;" : "+l"(d) : "l"(a), "l"(b));
}
__device__ __forceinline__ float2 unpack2(u64t v) {
    u32t lo, hi;
    asm("mov.b64 {%0, %1}, %2;" : "=r"(lo), "=r"(hi) : "l"(v));
    return make_float2(__uint_as_float(lo), __uint_as_float(hi));
}
// split (f0,f1) into packed bf16x2 hi and residual lo (f0 -> low 16 bits)
__device__ __forceinline__ void pack_split(float f0, float f1, u32t& hi, u32t& lo) {
    __nv_bfloat162 h = __float22bfloat162_rn(make_float2(f0, f1));
    float2 hf = __bfloat1622float2(h);
    __nv_bfloat162 l = __float22bfloat162_rn(make_float2(f0 - hf.x, f1 - hf.y));
    hi = *reinterpret_cast<u32t*>(&h);
    lo = *reinterpret_cast<u32t*>(&l);
}
// D += A(16x16 bf16, row) * B(16x8 bf16, col), f32 accumulate
__device__ __forceinline__ void mma_bf16(float& c0, float& c1, float& c2, float& c3,
                                         u32t a0, u32t a1, u32t a2, u32t a3,
                                         u32t b0, u32t b1) {
    asm volatile(
        "mma.sync.aligned.m16n8k16.row.col.f32.bf16.bf16.f32 "
        "{%0,%1,%2,%3}, {%4,%5,%6,%7}, {%8,%9}, {%0,%1,%2,%3};"
        : "+f"(c0), "+f"(c1), "+f"(c2), "+f"(c3)
        : "r"(a0), "r"(a1), "r"(a2), "r"(a3), "r"(b0), "r"(b1));
}

// ---- prepack: fp32 Wcat -> bf16 hi/lo in mma-fragment order ----
__global__ __launch_bounds__(256) void prepack_kernel(
    const float* __restrict__ wsss, const float* __restrict__ wvvs,
    const float* __restrict__ wssg, const float* __restrict__ wvvg)
{
    const int ci = blockIdx.x;
    const bool ssr = (ci < 128);
    const float* baseS = ssr ? (wsss + ci * 2048) : (wvvs + (ci - 128) * 2048);
    const float* baseG = ssr ? (wssg + ci * 1024) : (wvvg + (ci - 128) * 1024);
    for (int idx = threadIdx.x; idx < 768; idx += 256) {
        int ks = idx / 384;
        int rem = idx - ks * 384;
        int n = rem >> 2, qtr = rem & 3;
        int ka = ks * 16 + qtr * 2;   // pair a: rows ka, ka+1
        int kb = ka + 8;              // pair b: rows kb, kb+1
        float fa0, fa1, fb0, fb1;
        if (n < 64) {
            fa0 = baseS[ka * 64 + n];       fa1 = baseS[(ka + 1) * 64 + n];
            fb0 = baseS[kb * 64 + n];       fb1 = baseS[(kb + 1) * 64 + n];
        } else {
            int ng = n - 64;
            fa0 = baseG[ka * 32 + ng];      fa1 = baseG[(ka + 1) * 32 + ng];
            fb0 = baseG[kb * 32 + ng];      fb1 = baseG[(kb + 1) * 32 + ng];
        }
        u32t bh0, bl0, bh1, bl1;
        pack_split(fa0, fa1, bh0, bl0);
        pack_split(fb0, fb1, bh1, bl1);
        g_Wfrag[ci * 768 + idx] = make_uint4(bh0, bh1, bl0, bl1);
    }
}

__global__ __launch_bounds__(NT, 2) void equiconv_kernel(
    const float* __restrict__ fea_in1, const float* __restrict__ fea_in2,
    const float* __restrict__ fea_weight,
    const float* __restrict__ wsvv, const float* __restrict__ wvsv,
    const float* __restrict__ fw1, const float* __restrict__ fb1,
    const float* __restrict__ fw2, const float* __restrict__ fb2,
    const float* __restrict__ fw3, const float* __restrict__ fb3,
    float* __restrict__ out)
{
    extern __shared__ float smem[];
    float* s_x1sT = smem + OFF_X1ST;
    float* s_x2sT = smem + OFF_X2ST;
    float* s_x1v  = smem + OFF_X1V;
    float* s_x2v  = smem + OFF_X2V;
    float* s_un   = smem + OFF_UN;

    const int tid  = threadIdx.x;
    const int wid  = tid >> 5;          // 0..7
    const int lane = tid & 31;
    const int qid  = lane >> 2;         // 0..7
    const int qtr  = lane & 3;          // 0..3
    const int mstrip = wid & 3;         // M strip (16 edges)
    const int nhalf  = wid >> 2;        // N half (48 cols)
    const int em   = mstrip * 16 + qid; // A/C fragment row (edge)
    const int e8   = 8 * wid;           // vec phase: warp owns edges e8..e8+7
    const int e0g  = blockIdx.x * TE;
    // per-thread B-fragment base index within a (ci,ks) slab
    const int tb   = (nhalf * 48 + qid) * 4 + qtr;

    // ---- stage edge features ----
    for (int idx = tid; idx < TE * 160; idx += NT) {
        int e = idx / 160, c = idx - e * 160;
        int gE = e0g + e;
        float v1 = 0.f, v2 = 0.f;
        if (gE < E_TOT) { v1 = fea_in1[(long)gE * 160 + c]; v2 = fea_in2[(long)gE * 160 + c]; }
        if (c < 64) { s_x1sT[c * 68 + e] = v1; s_x2sT[c * 68 + e] = v2; }
        else        { s_x1v[e * 96 + (c - 64)] = v1; s_x2v[e * 96 + (c - 64)] = v2; }
    }

    // ---- MLP: 4 passes of 16 edges; wout -> registers ----
    float wr0[8], wr1[8], wr2[8], sgr[8];
    for (int p = 0; p < 4; p++) {
        const int eb0 = p * 16;
        __syncthreads();
        for (int idx = tid; idx < 16 * 128; idx += NT) {
            int e = idx >> 7, gE = e0g + eb0 + e;
            s_un[idx] = (gE < E_TOT) ? fea_weight[(long)gE * 128 + (idx & 127)] : 0.f;
        }
        __syncthreads();
        for (int o = tid; o < 16 * 64; o += NT) {      // h1 @2048
            int e = o >> 6, j = o & 63;
            float acc = fb1[j];
            const float* xe = s_un + e * 128;
            #pragma unroll 8
            for (int k = 0; k < 128; k++) acc += xe[k] * fw1[k * 64 + j];
            s_un[2048 + o] = acc * sigmoidf_(acc);
        }
        __syncthreads();
        for (int o = tid; o < 16 * 64; o += NT) {      // h2 @3072
            int e = o >> 6, j = o & 63;
            float acc = fb2[j];
            const float* xe = s_un + 2048 + e * 64;
            #pragma unroll 8
            for (int k = 0; k < 64; k++) acc += xe[k] * fw2[k * 64 + j];
            s_un[3072 + o] = acc * sigmoidf_(acc);
        }
        __syncthreads();
        for (int o = tid; o < 16 * 96; o += NT) {      // w3 @4096
            int e = o / 96, j = o - e * 96;
            float acc = fb3[j];
            const float* xe = s_un + 3072 + e * 64;
            #pragma unroll 8
            for (int k = 0; k < 64; k++) acc += xe[k] * fw3[k * 96 + j];
            s_un[4096 + o] = acc;
        }
        __syncthreads();
        if ((wid >> 1) == p) {
            #pragma unroll
            for (int j = 0; j < 8; j++) {
                int el = e8 - eb0 + j;
                wr0[j] = s_un[4096 + el * 96 + lane];
                wr1[j] = s_un[4096 + el * 96 + 32 + lane];
                wr2[j] = s_un[4096 + el * 96 + 64 + lane];
            }
        }
    }

    // ---- main GEMM: D[64][96] = P[64][5120] @ Wcat — BARRIER-FREE ----
    float acc[6][4];
    #pragma unroll
    for (int nt = 0; nt < 6; nt++)
        #pragma unroll
        for (int c = 0; c < 4; c++) acc[nt][c] = 0.f;

    for (int ci = 0; ci < NCHK; ci++) {
        const bool ssr = (ci < 128);
        #pragma unroll
        for (int ks = 0; ks < 2; ks++) {
            // B fragments: 6 coalesced LDG.128 (L1/L2 resident, 4-warp reuse)
            const uint4* bp = g_Wfrag + (ci * 2 + ks) * 384 + tb;
            uint4 bf[6];
            #pragma unroll
            for (int nt = 0; nt < 6; nt++) bf[nt] = bp[nt * 32];

            // A fragments (P hi/lo)
            u32t a0h, a1h, a2h, a3h, a0l, a1l, a2l, a3l;
            if (ssr) {
                const int u  = ci >> 1;
                const int v0 = (ci & 1) * 32 + ks * 16 + qtr * 2;
                float x1a = s_x1sT[u * 68 + em];
                float x1b = s_x1sT[u * 68 + em + 8];
                float ya0 = s_x2sT[(v0    ) * 68 + em], ya1 = s_x2sT[(v0 + 1) * 68 + em];
                float ya8 = s_x2sT[(v0 + 8) * 68 + em], ya9 = s_x2sT[(v0 + 9) * 68 + em];
                float yb0 = s_x2sT[(v0    ) * 68 + em + 8], yb1 = s_x2sT[(v0 + 1) * 68 + em + 8];
                float yb8 = s_x2sT[(v0 + 8) * 68 + em + 8], yb9 = s_x2sT[(v0 + 9) * 68 + em + 8];
                pack_split(x1a * ya0, x1a * ya1, a0h, a0l);
                pack_split(x1b * yb0, x1b * yb1, a1h, a1l);
                pack_split(x1a * ya8, x1a * ya9, a2h, a2l);
                pack_split(x1b * yb8, x1b * yb9, a3h, a3l);
            } else {
                const int u  = ci - 128;
                const int v0 = ks * 16 + qtr * 2;
                const float* va = s_x1v + em * 96 + u * 3;
                const float* vb = s_x1v + (em + 8) * 96 + u * 3;
                float p[8];
                #pragma unroll
                for (int q = 0; q < 4; q++) {
                    int v = v0 + (q & 1) + (q >> 1) * 8;    // v0, v0+1, v0+8, v0+9
                    const float* wa = s_x2v + em * 96 + v * 3;
                    const float* wb = s_x2v + (em + 8) * 96 + v * 3;
                    p[q]     = INV_SQRT3_F * (va[0] * wa[0] + va[1] * wa[1] + va[2] * wa[2]);
                    p[4 + q] = INV_SQRT3_F * (vb[0] * wb[0] + vb[1] * wb[1] + vb[2] * wb[2]);
                }
                pack_split(p[0], p[1], a0h, a0l);
                pack_split(p[4], p[5], a1h, a1l);
                pack_split(p[2], p[3], a2h, a2l);
                pack_split(p[6], p[7], a3h, a3l);
            }
            #pragma unroll
            for (int nt = 0; nt < 6; nt++) {
                mma_bf16(acc[nt][0], acc[nt][1], acc[nt][2], acc[nt][3],
                         a0h, a1h, a2h, a3h, bf[nt].x, bf[nt].y);
                mma_bf16(acc[nt][0], acc[nt][1], acc[nt][2], acc[nt][3],
                         a0h, a1h, a2h, a3h, bf[nt].z, bf[nt].w);
                mma_bf16(acc[nt][0], acc[nt][1], acc[nt][2], acc[nt][3],
                         a0l, a1l, a2l, a3l, bf[nt].x, bf[nt].y);
            }
        }
    }

    // ---- write D fragments to smem, then sc/g epilogue ----
    __syncthreads();
    float* Dbuf = s_un;   // [64][96]
    #pragma unroll
    for (int nt = 0; nt < 6; nt++) {
        int n = nhalf * 48 + nt * 8 + qtr * 2;
        *(float2*)(Dbuf + em * 96 + n)       = make_float2(acc[nt][0], acc[nt][1]);
        *(float2*)(Dbuf + (em + 8) * 96 + n) = make_float2(acc[nt][2], acc[nt][3]);
    }
    __syncthreads();
    #pragma unroll
    for (int j = 0; j < 8; j++) {
        int e = e8 + j, gE = e0g + e;
        float s0 = A_SC_F * Dbuf[e * 96 + lane];
        float s1 = A_SC_F * Dbuf[e * 96 + 32 + lane];
        sgr[j] = sigmoidf_(A_SC_F * Dbuf[e * 96 + 64 + lane]);
        if (gE < E_TOT) {
            long base = (long)gE * 160;
            out[base + lane]      = s0 * sigmoidf_(s0) * wr0[j];
            out[base + lane + 32] = s1 * sigmoidf_(s1) * wr1[j];
        }
    }

    // ---- vec phase: fp32 factored GEMMs, 8 edges/warp, f32x2 ----
    float vA[8][3];
    #pragma unroll
    for (int j = 0; j < 8; j++)
        #pragma unroll
        for (int c = 0; c < 3; c++) vA[j][c] = 0.f;

    // sv: B1[e,v,w] = sum_u x1s[e,u]*wsvv[u,v,w]; vec += B1 * x2v[e,v,i]
    for (int vc = 0; vc < 16; vc++) {
        __syncthreads();
        int v0 = vc * 2;
        #pragma unroll
        for (int i = 0; i < 4; i++) {
            int fidx = tid + NT * i;          // 1024 float4 = [128 rows][32]
            int r = fidx >> 3, c4 = fidx & 7;
            *(float4*)(s_un + r * 32 + c4 * 4) =
                *(const float4*)(wsvv + (r >> 1) * 1024 + (v0 + (r & 1)) * 32 + c4 * 4);
        }
        __syncthreads();
        u64t b0p[4] = {0, 0, 0, 0}, b1p[4] = {0, 0, 0, 0};
        const float* wv = s_un + lane;
        #pragma unroll 8
        for (int u = 0; u < 64; u++) {
            ulonglong2 x0 = *(const ulonglong2*)(s_x1sT + u * 68 + e8);
            ulonglong2 x1 = *(const ulonglong2*)(s_x1sT + u * 68 + e8 + 4);
            u64t w0 = splat2(wv[(u * 2 + 0) * 32]);
            u64t w1 = splat2(wv[(u * 2 + 1) * 32]);
            fma2(b0p[0], x0.x, w0); fma2(b0p[1], x0.y, w0);
            fma2(b0p[2], x1.x, w0); fma2(b0p[3], x1.y, w0);
            fma2(b1p[0], x0.x, w1); fma2(b1p[1], x0.y, w1);
            fma2(b1p[2], x1.x, w1); fma2(b1p[3], x1.y, w1);
        }
        float B0[8], B1[8];
        #pragma unroll
        for (int k2 = 0; k2 < 4; k2++) {
            float2 f = unpack2(b0p[k2]); B0[2 * k2] = f.x; B0[2 * k2 + 1] = f.y;
            float2 g = unpack2(b1p[k2]); B1[2 * k2] = g.x; B1[2 * k2 + 1] = g.y;
        }
        #pragma unroll
        for (int j = 0; j < 8; j++) {
            const float* xv = s_x2v + (e8 + j) * 96 + v0 * 3;
            vA[j][0] += B0[j] * xv[0] + B1[j] * xv[3];
            vA[j][1] += B0[j] * xv[1] + B1[j] * xv[4];
            vA[j][2] += B0[j] * xv[2] + B1[j] * xv[5];
        }
    }
    // vs: B2[e,u,w] = sum_v x2s[e,v]*wvsv[u,v,w]; vec += B2 * x1v[e,u,i]
    for (int uc = 0; uc < 16; uc++) {
        __syncthreads();
        int u0 = uc * 2;
        #pragma unroll
        for (int i = 0; i < 4; i++) {
            int fidx = tid + NT * i;          // [128 rows][32]: row = uu*64 + v
            int r = fidx >> 3, c4 = fidx & 7;
            *(float4*)(s_un + r * 32 + c4 * 4) =
                *(const float4*)(wvsv + (u0 + (r >> 6)) * 2048 + (r & 63) * 32 + c4 * 4);
        }
        __syncthreads();
        u64t b0p[4] = {0, 0, 0, 0}, b1p[4] = {0, 0, 0, 0};
        const float* wv = s_un + lane;
        #pragma unroll 8
        for (int v = 0; v < 64; v++) {
            ulonglong2 x0 = *(const ulonglong2*)(s_x2sT + v * 68 + e8);
            ulonglong2 x1 = *(const ulonglong2*)(s_x2sT + v * 68 + e8 + 4);
            u64t w0 = splat2(wv[v * 32]);
            u64t w1 = splat2(wv[(64 + v) * 32]);
            fma2(b0p[0], x0.x, w0); fma2(b0p[1], x0.y, w0);
            fma2(b0p[2], x1.x, w0); fma2(b0p[3], x1.y, w0);
            fma2(b1p[0], x0.x, w1); fma2(b1p[1], x0.y, w1);
            fma2(b1p[2], x1.x, w1); fma2(b1p[3], x1.y, w1);
        }
        float B0[8], B1[8];
        #pragma unroll
        for (int k2 = 0; k2 < 4; k2++) {
            float2 f = unpack2(b0p[k2]); B0[2 * k2] = f.x; B0[2 * k2 + 1] = f.y;
            float2 g = unpack2(b1p[k2]); B1[2 * k2] = g.x; B1[2 * k2 + 1] = g.y;
        }
        #pragma unroll
        for (int j = 0; j < 8; j++) {
            const float* xv = s_x1v + (e8 + j) * 96 + u0 * 3;
            vA[j][0] += B0[j] * xv[0] + B1[j] * xv[3];
            vA[j][1] += B0[j] * xv[1] + B1[j] * xv[4];
            vA[j][2] += B0[j] * xv[2] + B1[j] * xv[5];
        }
    }
    #pragma unroll
    for (int j = 0; j < 8; j++) {
        int gE = e0g + e8 + j;
        if (gE < E_TOT) {
            float m = A_VEC_F * sgr[j] * wr2[j];
            float* o = out + (long)gE * 160 + 64 + lane * 3;
            o[0] = vA[j][0] * m;
            o[1] = vA[j][1] * m;
            o[2] = vA[j][2] * m;
        }
    }
}

extern "C" void kernel_launch(void* const* d_in, const int* in_sizes, int n_in,
                              void* d_out, int out_size) {
    (void)in_sizes; (void)n_in; (void)out_size;
    const float* fea_in1    = (const float*)d_in[0];
    const float* fea_in2    = (const float*)d_in[1];
    const float* fea_weight = (const float*)d_in[2];
    const float* w_ss_s     = (const float*)d_in[3];
    const float* w_vv_s     = (const float*)d_in[4];
    const float* w_ss_g     = (const float*)d_in[5];
    const float* w_vv_g     = (const float*)d_in[6];
    const float* w_sv_v     = (const float*)d_in[7];
    const float* w_vs_v     = (const float*)d_in[8];
    const float* fc_w1      = (const float*)d_in[9];
    const float* fc_b1      = (const float*)d_in[10];
    const float* fc_w2      = (const float*)d_in[11];
    const float* fc_b2      = (const float*)d_in[12];
    const float* fc_w3      = (const float*)d_in[13];
    const float* fc_b3      = (const float*)d_in[14];
    float* out = (float*)d_out;

    cudaFuncSetAttribute(equiconv_kernel,
                         cudaFuncAttributeMaxDynamicSharedMemorySize,
                         SMEM_FLOATS * sizeof(float));
    cudaFuncSetAttribute(equiconv_kernel,
                         cudaFuncAttributePreferredSharedMemoryCarveout,
                         cudaSharedmemCarveoutMaxShared);

    prepack_kernel<<<NCHK, 256>>>(w_ss_s, w_vv_s, w_ss_g, w_vv_g);

    dim3 grid((E_TOT + TE - 1) / TE);   // 313
    dim3 block(NT);
    equiconv_kernel<<<grid, block, SMEM_FLOATS * sizeof(float)>>>(
        fea_in1, fea_in2, fea_weight,
        w_sv_v, w_vs_v,
        fc_w1, fc_b1, fc_w2, fc_b2, fc_w3, fc_b3,
        out);
}